// round 5
// baseline (speedup 1.0000x reference)
#include <cuda_runtime.h>

#define L_DIM 512
#define B_DIM 64
#define H_DIM 1024

// Scratch (no allocations allowed). Zero-initialized at module load;
// g_cnt is reset to 0 by the kernel itself each run (graph-replay safe).
__device__ __align__(16) float g_u[H_DIM];
__device__ float g_attn[B_DIM * L_DIM];
__device__ int   g_cnt[B_DIM];

// ---------------------------------------------------------------------------
// K1: u[h] = sum_k W_att[k, H + h] * v[k]      (atomic-free)
// 32 blocks x 1024 threads. Block owns 32 h-columns.
// Thread t: hl = t&31 (h within block), kg = t>>5 (k-group, 32 groups).
// Each thread streams 32 rows (k = kg*32 + i) with coalesced 128B row reads,
// partials reduced through 4KB smem. Deterministic, no memset needed.
// ---------------------------------------------------------------------------
__global__ void __launch_bounds__(1024) compute_u_kernel(const float* __restrict__ W_att,
                                                         const float* __restrict__ vec) {
    __shared__ float red[32 * 32];
    const int t  = threadIdx.x;
    const int hl = t & 31;
    const int kg = t >> 5;
    const int h  = blockIdx.x * 32 + hl;

    const float* wp = W_att + (size_t)(kg * 32) * (2 * H_DIM) + H_DIM + h;

    float acc = 0.f;
    #pragma unroll 8
    for (int i = 0; i < 32; i++) {
        const float vk = __ldg(&vec[kg * 32 + i]);
        acc += wp[(size_t)i * (2 * H_DIM)] * vk;
    }
    red[kg * 32 + hl] = acc;
    __syncthreads();

    if (t < 32) {
        float s = 0.f;
        #pragma unroll
        for (int g = 0; g < 32; g++) s += red[g * 32 + t];   // bank-conflict-free
        g_u[blockIdx.x * 32 + t] = s;
    }
}

// ---------------------------------------------------------------------------
// K2 (+fused softmax): attn[b,l] = <hs_encoder[l,b,:], u>, then the warp that
// completes the 512th row of a batch b performs softmax over that batch.
// One warp per (l,b) row, 512-thread blocks, float4 loads, u in shared.
// No warp ever waits (the last arriver does the work) -> no deadlock risk.
// ---------------------------------------------------------------------------
__global__ void __launch_bounds__(512) dot_kernel(const float* __restrict__ hs,
                                                  float* __restrict__ out) {
    __shared__ float4 su[H_DIM / 4];          // 4 KB
    const int t = threadIdx.x;
    if (t < H_DIM / 4) su[t] = reinterpret_cast<const float4*>(g_u)[t];
    __syncthreads();

    const int warp = t >> 5;
    const int lane = t & 31;
    const int row  = blockIdx.x * 16 + warp;  // row = l*B + b

    const float4* rp = reinterpret_cast<const float4*>(hs) + (size_t)row * (H_DIM / 4);

    float acc = 0.f;
    #pragma unroll
    for (int j = 0; j < 8; j++) {
        const int idx = lane + j * 32;
        const float4 x = rp[idx];
        const float4 u = su[idx];
        acc += x.x * u.x + x.y * u.y + x.z * u.z + x.w * u.w;
    }
    #pragma unroll
    for (int o = 16; o; o >>= 1)
        acc += __shfl_xor_sync(0xffffffffu, acc, o);

    const int l = row >> 6;                   // row / B
    const int b = row & 63;                   // row % B

    int old = 0;
    if (lane == 0) {
        g_attn[b * L_DIM + l] = acc;
        __threadfence();                      // make write visible before count
        old = atomicAdd(&g_cnt[b], 1);
    }
    old = __shfl_sync(0xffffffffu, old, 0);

    if (old == L_DIM - 1) {
        // This warp saw the last row of batch b complete: do its softmax.
        __threadfence();                      // order reads after the atomic
        float a[16];
        float m = -3.4e38f;
        #pragma unroll
        for (int j = 0; j < 16; j++) {
            a[j] = __ldcg(&g_attn[b * L_DIM + lane + j * 32]);  // L2-coherent
            m = fmaxf(m, a[j]);
        }
        #pragma unroll
        for (int o = 16; o; o >>= 1) m = fmaxf(m, __shfl_xor_sync(0xffffffffu, m, o));

        float s = 0.f;
        #pragma unroll
        for (int j = 0; j < 16; j++) {
            a[j] = expf(a[j] - m);
            s += a[j];
        }
        #pragma unroll
        for (int o = 16; o; o >>= 1) s += __shfl_xor_sync(0xffffffffu, s, o);

        const float inv = 1.f / s;
        #pragma unroll
        for (int j = 0; j < 16; j++)
            out[b * L_DIM + lane + j * 32] = a[j] * inv;

        if (lane == 0) g_cnt[b] = 0;          // reset for next graph replay
    }
}

// ---------------------------------------------------------------------------
// Inputs (metadata order): hidden, hs_encoder, W_att, b_att, vector
// hidden / b_att / Wh are mathematically dead (softmax shift invariance).
// ---------------------------------------------------------------------------
extern "C" void kernel_launch(void* const* d_in, const int* in_sizes, int n_in,
                              void* d_out, int out_size) {
    const float* hs  = (const float*)d_in[1];   // (512, 64, 1024)
    const float* W   = (const float*)d_in[2];   // (1024, 2048)
    const float* vec = (const float*)d_in[4];   // (1024, 1)
    float* out = (float*)d_out;                 // (64, 1, 512)

    compute_u_kernel<<<H_DIM / 32, 1024>>>(W, vec);
    dot_kernel<<<(L_DIM * B_DIM) / 16, 512>>>(hs, out);
}

// round 7
// speedup vs baseline: 1.3151x; 1.3151x over previous
#include <cuda_runtime.h>

#define L_DIM 512
#define B_DIM 64
#define H_DIM 1024

// Scratch (no allocations allowed)
__device__ __align__(16) float g_u[H_DIM];
__device__ float g_attn[B_DIM * L_DIM];

// ---------------------------------------------------------------------------
// K1: u[h] = sum_k W_att[k, H + h] * v[k]      (atomic-free)
// 32 blocks x 1024 threads. Block owns 32 h-columns.
// Thread t: hl = t&31 (h within block), kg = t>>5 (k-group, 32 groups).
// Each thread streams 32 rows (coalesced 128B row segments), partials
// reduced through 4KB smem. Deterministic, no memset, no atomics.
// ---------------------------------------------------------------------------
__global__ void __launch_bounds__(1024) compute_u_kernel(const float* __restrict__ W_att,
                                                         const float* __restrict__ vec) {
    __shared__ float red[32 * 32];
    const int t  = threadIdx.x;
    const int hl = t & 31;
    const int kg = t >> 5;
    const int h  = blockIdx.x * 32 + hl;

    const float* wp = W_att + (size_t)(kg * 32) * (2 * H_DIM) + H_DIM + h;

    float acc = 0.f;
    #pragma unroll 8
    for (int i = 0; i < 32; i++) {
        const float vk = __ldg(&vec[kg * 32 + i]);
        acc += wp[(size_t)i * (2 * H_DIM)] * vk;
    }
    red[kg * 32 + hl] = acc;
    __syncthreads();

    if (t < 32) {
        float s = 0.f;
        #pragma unroll
        for (int g = 0; g < 32; g++) s += red[g * 32 + t];   // bank-conflict-free
        g_u[blockIdx.x * 32 + t] = s;
    }
}

// ---------------------------------------------------------------------------
// K2: attn[b,l] = <hs_encoder[l,b,:], u>   (the 134 MB streaming kernel)
// One warp per (l,b) row, 256-thread blocks. float4 loads (8 per lane,
// MLP=8), u staged in shared. NO fences, NO atomics in the hot path.
// ---------------------------------------------------------------------------
__global__ void __launch_bounds__(256) dot_kernel(const float* __restrict__ hs) {
    __shared__ float4 su[H_DIM / 4];          // 4 KB
    const int t = threadIdx.x;
    su[t] = reinterpret_cast<const float4*>(g_u)[t];
    __syncthreads();

    const int warp = t >> 5;
    const int lane = t & 31;
    const int row  = blockIdx.x * 8 + warp;   // row = l*B + b

    const float4* rp = reinterpret_cast<const float4*>(hs) + (size_t)row * (H_DIM / 4);

    float acc = 0.f;
    #pragma unroll
    for (int j = 0; j < 8; j++) {
        const int idx = lane + j * 32;
        const float4 x = rp[idx];
        const float4 u = su[idx];
        acc += x.x * u.x + x.y * u.y + x.z * u.z + x.w * u.w;
    }
    #pragma unroll
    for (int o = 16; o; o >>= 1)
        acc += __shfl_xor_sync(0xffffffffu, acc, o);

    if (lane == 0) {
        const int l = row >> 6;               // row / B
        const int b = row & 63;               // row % B
        g_attn[b * L_DIM + l] = acc;
    }
}

// ---------------------------------------------------------------------------
// K3: out[b, 0, l] = softmax_l(attn[b, l]).  One block per batch, 512 threads.
// ---------------------------------------------------------------------------
__global__ void __launch_bounds__(512) softmax_kernel(float* __restrict__ out) {
    __shared__ float sm[16];
    const int b = blockIdx.x;
    const int t = threadIdx.x;                // 0..511
    const int lane = t & 31, w = t >> 5;

    const float a = g_attn[b * L_DIM + t];

    float m = a;
    #pragma unroll
    for (int o = 16; o; o >>= 1) m = fmaxf(m, __shfl_xor_sync(0xffffffffu, m, o));
    if (lane == 0) sm[w] = m;
    __syncthreads();
    float M = sm[0];
    #pragma unroll
    for (int i = 1; i < 16; i++) M = fmaxf(M, sm[i]);
    __syncthreads();

    const float e = expf(a - M);

    float s = e;
    #pragma unroll
    for (int o = 16; o; o >>= 1) s += __shfl_xor_sync(0xffffffffu, s, o);
    if (lane == 0) sm[w] = s;
    __syncthreads();
    float S = sm[0];
    #pragma unroll
    for (int i = 1; i < 16; i++) S += sm[i];

    out[b * L_DIM + t] = e / S;
}

// ---------------------------------------------------------------------------
// Inputs (metadata order): hidden, hs_encoder, W_att, b_att, vector
// hidden / b_att / Wh are mathematically dead (softmax shift invariance).
// ---------------------------------------------------------------------------
extern "C" void kernel_launch(void* const* d_in, const int* in_sizes, int n_in,
                              void* d_out, int out_size) {
    const float* hs  = (const float*)d_in[1];   // (512, 64, 1024)
    const float* W   = (const float*)d_in[2];   // (1024, 2048)
    const float* vec = (const float*)d_in[4];   // (1024, 1)
    float* out = (float*)d_out;                 // (64, 1, 512)

    compute_u_kernel<<<H_DIM / 32, 1024>>>(W, vec);
    dot_kernel<<<(L_DIM * B_DIM) / 8, 256>>>(hs);
    softmax_kernel<<<B_DIM, 512>>>(out);
}

// round 11
// speedup vs baseline: 1.3811x; 1.0502x over previous
#include <cuda_runtime.h>

#define L_DIM 512
#define B_DIM 64
#define H_DIM 1024

// Scratch (no allocations allowed)
__device__ __align__(16) float g_u_part[4 * H_DIM];   // 4 k-quarter partials
__device__ float g_attn[B_DIM * L_DIM];

// ---------------------------------------------------------------------------
// K1: partial u. Grid (32 h-groups, 4 k-quarters) = 128 blocks x 1024 thr.
// Block (hg,kq): owns h-columns [hg*32, hg*32+32) and k-rows [kq*256, +256).
// Thread t: hl = t&31, kg = t>>5; each thread streams 8 rows (coalesced
// 128B row segments), partials reduced through 4KB smem. Atomic-free.
// ---------------------------------------------------------------------------
__global__ void __launch_bounds__(1024) compute_u_kernel(const float* __restrict__ W_att,
                                                         const float* __restrict__ vec) {
    __shared__ float red[32 * 32];
    const int t  = threadIdx.x;
    const int hl = t & 31;
    const int kg = t >> 5;
    const int h  = blockIdx.x * 32 + hl;
    const int k0 = blockIdx.y * 256;

    const float* wp = W_att + (size_t)(k0 + kg) * (2 * H_DIM) + H_DIM + h;

    float acc = 0.f;
    #pragma unroll
    for (int i = 0; i < 8; i++) {
        const int k = k0 + kg + i * 32;
        const float vk = __ldg(&vec[k]);
        acc += wp[(size_t)(i * 32) * (2 * H_DIM)] * vk;
    }
    red[kg * 32 + hl] = acc;
    __syncthreads();

    if (t < 32) {
        float s = 0.f;
        #pragma unroll
        for (int g = 0; g < 32; g++) s += red[g * 32 + t];   // bank-conflict-free
        g_u_part[blockIdx.y * H_DIM + blockIdx.x * 32 + t] = s;
    }
}

// ---------------------------------------------------------------------------
// K2: attn[b,l] = <hs_encoder[l,b,:], u>   (the 134 MB streaming kernel)
// One warp per (l,b) row, 512-thread blocks. The u-staging prologue sums
// the 4 k-quarter partials (L2-hot). Hot loop: float4 loads, MLP=8,
// NO fences, NO atomics.
// ---------------------------------------------------------------------------
__global__ void __launch_bounds__(512) dot_kernel(const float* __restrict__ hs) {
    __shared__ float4 su[H_DIM / 4];          // 4 KB
    const int t = threadIdx.x;
    if (t < H_DIM / 4) {
        const float4* p = reinterpret_cast<const float4*>(g_u_part);
        float4 a = p[t];
        const float4 b = p[t + 256];
        const float4 c = p[t + 512];
        const float4 d = p[t + 768];
        a.x += b.x + c.x + d.x;
        a.y += b.y + c.y + d.y;
        a.z += b.z + c.z + d.z;
        a.w += b.w + c.w + d.w;
        su[t] = a;
    }
    __syncthreads();

    const int warp = t >> 5;
    const int lane = t & 31;
    const int row  = blockIdx.x * 16 + warp;  // row = l*B + b

    const float4* rp = reinterpret_cast<const float4*>(hs) + (size_t)row * (H_DIM / 4);

    float acc = 0.f;
    #pragma unroll
    for (int j = 0; j < 8; j++) {
        const int idx = lane + j * 32;
        const float4 x = rp[idx];
        const float4 u = su[idx];
        acc += x.x * u.x + x.y * u.y + x.z * u.z + x.w * u.w;
    }
    #pragma unroll
    for (int o = 16; o; o >>= 1)
        acc += __shfl_xor_sync(0xffffffffu, acc, o);

    if (lane == 0) {
        const int l = row >> 6;               // row / B
        const int b = row & 63;               // row % B
        g_attn[b * L_DIM + l] = acc;
    }
}

// ---------------------------------------------------------------------------
// K3: out[b, 0, l] = softmax_l(attn[b, l]).  One block per batch, 512 threads.
// ---------------------------------------------------------------------------
__global__ void __launch_bounds__(512) softmax_kernel(float* __restrict__ out) {
    __shared__ float sm[16];
    const int b = blockIdx.x;
    const int t = threadIdx.x;                // 0..511
    const int lane = t & 31, w = t >> 5;

    const float a = g_attn[b * L_DIM + t];

    float m = a;
    #pragma unroll
    for (int o = 16; o; o >>= 1) m = fmaxf(m, __shfl_xor_sync(0xffffffffu, m, o));
    if (lane == 0) sm[w] = m;
    __syncthreads();
    float M = sm[0];
    #pragma unroll
    for (int i = 1; i < 16; i++) M = fmaxf(M, sm[i]);
    __syncthreads();

    const float e = expf(a - M);

    float s = e;
    #pragma unroll
    for (int o = 16; o; o >>= 1) s += __shfl_xor_sync(0xffffffffu, s, o);
    if (lane == 0) sm[w] = s;
    __syncthreads();
    float S = sm[0];
    #pragma unroll
    for (int i = 1; i < 16; i++) S += sm[i];

    out[b * L_DIM + t] = e / S;
}

// ---------------------------------------------------------------------------
// Inputs (metadata order): hidden, hs_encoder, W_att, b_att, vector
// hidden / b_att / Wh are mathematically dead (softmax shift invariance).
// ---------------------------------------------------------------------------
extern "C" void kernel_launch(void* const* d_in, const int* in_sizes, int n_in,
                              void* d_out, int out_size) {
    const float* hs  = (const float*)d_in[1];   // (512, 64, 1024)
    const float* W   = (const float*)d_in[2];   // (1024, 2048)
    const float* vec = (const float*)d_in[4];   // (1024, 1)
    float* out = (float*)d_out;                 // (64, 1, 512)

    dim3 g1(H_DIM / 32, 4);
    compute_u_kernel<<<g1, 1024>>>(W, vec);
    dot_kernel<<<(L_DIM * B_DIM) / 16, 512>>>(hs);
    softmax_kernel<<<B_DIM, 512>>>(out);
}

// round 13
// speedup vs baseline: 1.3998x; 1.0135x over previous
#include <cuda_runtime.h>

#define L_DIM 512
#define B_DIM 64
#define H_DIM 1024

// Scratch (no allocations allowed). Zero-initialized at module load.
__device__ __align__(16) float g_u_part[4 * H_DIM];   // 4 k-quarter partials
__device__ __align__(16) float g_u[H_DIM];            // finalized u
__device__ int   g_ctr[H_DIM / 32];                   // per-hg arrival counters
__device__ float g_attn[B_DIM * L_DIM];

// ---------------------------------------------------------------------------
// K1: partial u + in-kernel finalize.
// Grid (32 h-groups, 4 k-quarters) = 128 blocks x 1024 thr.
// Block (hg,kq): h-cols [hg*32,+32), k-rows [kq*256,+256). Thread streams 8
// coalesced 128B row segments; smem reduce; warp 0 writes the partial.
// The LAST block per hg (counter) sums the 4 partials -> g_u (fixed order,
// deterministic) and resets the counter for graph replay.
// ---------------------------------------------------------------------------
__global__ void __launch_bounds__(1024) compute_u_kernel(const float* __restrict__ W_att,
                                                         const float* __restrict__ vec) {
    __shared__ float red[32 * 32];
    const int t  = threadIdx.x;
    const int hl = t & 31;
    const int kg = t >> 5;
    const int h  = blockIdx.x * 32 + hl;
    const int k0 = blockIdx.y * 256;

    const float* wp = W_att + (size_t)(k0 + kg) * (2 * H_DIM) + H_DIM + h;

    float acc = 0.f;
    #pragma unroll
    for (int i = 0; i < 8; i++) {
        const float vk = __ldg(&vec[k0 + kg + i * 32]);
        acc += wp[(size_t)(i * 32) * (2 * H_DIM)] * vk;
    }
    red[kg * 32 + hl] = acc;
    __syncthreads();

    if (t < 32) {                              // warp 0 only
        float s = 0.f;
        #pragma unroll
        for (int g = 0; g < 32; g++) s += red[g * 32 + t];   // bank-conflict-free
        g_u_part[blockIdx.y * H_DIM + blockIdx.x * 32 + t] = s;
        __threadfence();                       // release this thread's part write
        __syncwarp();

        int old = 0;
        if (t == 0) old = atomicAdd(&g_ctr[blockIdx.x], 1);
        old = __shfl_sync(0xffffffffu, old, 0);

        if (old == 3) {                        // last kq block for this hg
            __threadfence();                   // acquire: order reads after atomic
            const int hh = blockIdx.x * 32 + t;
            float v = __ldcg(&g_u_part[0 * H_DIM + hh]);
            v      += __ldcg(&g_u_part[1 * H_DIM + hh]);
            v      += __ldcg(&g_u_part[2 * H_DIM + hh]);
            v      += __ldcg(&g_u_part[3 * H_DIM + hh]);
            g_u[hh] = v;
            if (t == 0) g_ctr[blockIdx.x] = 0; // reset for next replay
        }
    }
}

// ---------------------------------------------------------------------------
// K2: attn[b,l] = <hs_encoder[l,b,:], u>   (the 134 MB streaming kernel)
// One warp per (l,b) row, 512-thread blocks, grid 2048. Staging: ONE float4
// per thread from finalized g_u (8 MB total L2, was 32 MB). Hot loop:
// __ldcs float4 loads (evict-first, read-once), MLP=8, no fences/atomics.
// ---------------------------------------------------------------------------
__global__ void __launch_bounds__(512) dot_kernel(const float* __restrict__ hs) {
    __shared__ float4 su[H_DIM / 4];          // 4 KB
    const int t = threadIdx.x;
    if (t < H_DIM / 4)
        su[t] = __ldcg(reinterpret_cast<const float4*>(g_u) + t);
    __syncthreads();

    const int warp = t >> 5;
    const int lane = t & 31;
    const int row  = blockIdx.x * 16 + warp;  // row = l*B + b

    const float4* rp = reinterpret_cast<const float4*>(hs) + (size_t)row * (H_DIM / 4);

    float acc = 0.f;
    #pragma unroll
    for (int j = 0; j < 8; j++) {
        const int idx = lane + j * 32;
        const float4 x = __ldcs(rp + idx);    // streaming, evict-first
        const float4 u = su[idx];
        acc += x.x * u.x + x.y * u.y + x.z * u.z + x.w * u.w;
    }
    #pragma unroll
    for (int o = 16; o; o >>= 1)
        acc += __shfl_xor_sync(0xffffffffu, acc, o);

    if (lane == 0) {
        const int l = row >> 6;               // row / B
        const int b = row & 63;               // row % B
        g_attn[b * L_DIM + l] = acc;
    }
}

// ---------------------------------------------------------------------------
// K3: out[b, 0, l] = softmax_l(attn[b, l]).  One block per batch, 512 threads.
// ---------------------------------------------------------------------------
__global__ void __launch_bounds__(512) softmax_kernel(float* __restrict__ out) {
    __shared__ float sm[16];
    const int b = blockIdx.x;
    const int t = threadIdx.x;                // 0..511
    const int lane = t & 31, w = t >> 5;

    const float a = g_attn[b * L_DIM + t];

    float m = a;
    #pragma unroll
    for (int o = 16; o; o >>= 1) m = fmaxf(m, __shfl_xor_sync(0xffffffffu, m, o));
    if (lane == 0) sm[w] = m;
    __syncthreads();
    float M = sm[0];
    #pragma unroll
    for (int i = 1; i < 16; i++) M = fmaxf(M, sm[i]);
    __syncthreads();

    const float e = expf(a - M);

    float s = e;
    #pragma unroll
    for (int o = 16; o; o >>= 1) s += __shfl_xor_sync(0xffffffffu, s, o);
    if (lane == 0) sm[w] = s;
    __syncthreads();
    float S = sm[0];
    #pragma unroll
    for (int i = 1; i < 16; i++) S += sm[i];

    out[b * L_DIM + t] = e / S;
}

// ---------------------------------------------------------------------------
// Inputs (metadata order): hidden, hs_encoder, W_att, b_att, vector
// hidden / b_att / Wh are mathematically dead (softmax shift invariance).
// ---------------------------------------------------------------------------
extern "C" void kernel_launch(void* const* d_in, const int* in_sizes, int n_in,
                              void* d_out, int out_size) {
    const float* hs  = (const float*)d_in[1];   // (512, 64, 1024)
    const float* W   = (const float*)d_in[2];   // (1024, 2048)
    const float* vec = (const float*)d_in[4];   // (1024, 1)
    float* out = (float*)d_out;                 // (64, 1, 512)

    dim3 g1(H_DIM / 32, 4);
    compute_u_kernel<<<g1, 1024>>>(W, vec);
    dot_kernel<<<(L_DIM * B_DIM) / 16, 512>>>(hs);
    softmax_kernel<<<B_DIM, 512>>>(out);
}

// round 14
// speedup vs baseline: 1.4042x; 1.0031x over previous
#include <cuda_runtime.h>

#define L_DIM 512
#define B_DIM 64
#define H_DIM 1024
#define K2_GRID 296   // 2 blocks per SM on 148 SMs

// Scratch (no allocations allowed)
__device__ __align__(16) float g_u_part[4 * H_DIM];   // 4 k-quarter partials
__device__ float g_attn[B_DIM * L_DIM];

// ---------------------------------------------------------------------------
// K1: partial u. Grid (32 h-groups, 4 k-quarters) = 128 blocks x 1024 thr.
// Block (hg,kq): h-cols [hg*32,+32), k-rows [kq*256,+256). Thread streams 8
// coalesced 128B row segments; smem reduce; warp 0 writes the partial.
// Atomic-free, fence-free (clean R11 version, measured 4.96us).
// ---------------------------------------------------------------------------
__global__ void __launch_bounds__(1024) compute_u_kernel(const float* __restrict__ W_att,
                                                         const float* __restrict__ vec) {
    __shared__ float red[32 * 32];
    const int t  = threadIdx.x;
    const int hl = t & 31;
    const int kg = t >> 5;
    const int h  = blockIdx.x * 32 + hl;
    const int k0 = blockIdx.y * 256;

    const float* wp = W_att + (size_t)(k0 + kg) * (2 * H_DIM) + H_DIM + h;

    float acc = 0.f;
    #pragma unroll
    for (int i = 0; i < 8; i++) {
        const float vk = __ldg(&vec[k0 + kg + i * 32]);
        acc += wp[(size_t)(i * 32) * (2 * H_DIM)] * vk;
    }
    red[kg * 32 + hl] = acc;
    __syncthreads();

    if (t < 32) {
        float s = 0.f;
        #pragma unroll
        for (int g = 0; g < 32; g++) s += red[g * 32 + t];   // bank-conflict-free
        g_u_part[blockIdx.y * H_DIM + blockIdx.x * 32 + t] = s;
    }
}

// ---------------------------------------------------------------------------
// K2: attn[b,l] = <hs_encoder[l,b,:], u>   (the 134 MB streaming kernel)
// PERSISTENT: 296 blocks x 512 thr; staging (sum of 4 k-partials) happens
// once per block (296 x 16KB = 4.7MB L2), then each warp grid-strides over
// rows (~7 per warp). Hot loop: __ldcs float4 (evict-first), MLP=8 per row
// plus cross-iteration ILP. NO fences, NO atomics.
// ---------------------------------------------------------------------------
__global__ void __launch_bounds__(512) dot_kernel(const float* __restrict__ hs) {
    __shared__ float4 su[H_DIM / 4];          // 4 KB
    const int t = threadIdx.x;
    if (t < H_DIM / 4) {
        const float4* p = reinterpret_cast<const float4*>(g_u_part);
        float4 a = p[t];
        const float4 b = p[t + 256];
        const float4 c = p[t + 512];
        const float4 d = p[t + 768];
        a.x += b.x + c.x + d.x;
        a.y += b.y + c.y + d.y;
        a.z += b.z + c.z + d.z;
        a.w += b.w + c.w + d.w;
        su[t] = a;
    }
    __syncthreads();

    const int warp  = t >> 5;
    const int lane  = t & 31;
    const int nwarp = K2_GRID * 16;           // total warps in grid

    for (int row = blockIdx.x * 16 + warp; row < L_DIM * B_DIM; row += nwarp) {
        const float4* rp = reinterpret_cast<const float4*>(hs) + (size_t)row * (H_DIM / 4);

        float acc = 0.f;
        #pragma unroll
        for (int j = 0; j < 8; j++) {
            const int idx = lane + j * 32;
            const float4 x = __ldcs(rp + idx);    // streaming, evict-first
            const float4 u = su[idx];
            acc += x.x * u.x + x.y * u.y + x.z * u.z + x.w * u.w;
        }
        #pragma unroll
        for (int o = 16; o; o >>= 1)
            acc += __shfl_xor_sync(0xffffffffu, acc, o);

        if (lane == 0) {
            const int l = row >> 6;               // row / B
            const int b = row & 63;               // row % B
            g_attn[b * L_DIM + l] = acc;
        }
    }
}

// ---------------------------------------------------------------------------
// K3: out[b, 0, l] = softmax_l(attn[b, l]).  One block per batch, 512 threads.
// ---------------------------------------------------------------------------
__global__ void __launch_bounds__(512) softmax_kernel(float* __restrict__ out) {
    __shared__ float sm[16];
    const int b = blockIdx.x;
    const int t = threadIdx.x;                // 0..511
    const int lane = t & 31, w = t >> 5;

    const float a = g_attn[b * L_DIM + t];

    float m = a;
    #pragma unroll
    for (int o = 16; o; o >>= 1) m = fmaxf(m, __shfl_xor_sync(0xffffffffu, m, o));
    if (lane == 0) sm[w] = m;
    __syncthreads();
    float M = sm[0];
    #pragma unroll
    for (int i = 1; i < 16; i++) M = fmaxf(M, sm[i]);
    __syncthreads();

    const float e = expf(a - M);

    float s = e;
    #pragma unroll
    for (int o = 16; o; o >>= 1) s += __shfl_xor_sync(0xffffffffu, s, o);
    if (lane == 0) sm[w] = s;
    __syncthreads();
    float S = sm[0];
    #pragma unroll
    for (int i = 1; i < 16; i++) S += sm[i];

    out[b * L_DIM + t] = e / S;
}

// ---------------------------------------------------------------------------
// Inputs (metadata order): hidden, hs_encoder, W_att, b_att, vector
// hidden / b_att / Wh are mathematically dead (softmax shift invariance).
// ---------------------------------------------------------------------------
extern "C" void kernel_launch(void* const* d_in, const int* in_sizes, int n_in,
                              void* d_out, int out_size) {
    const float* hs  = (const float*)d_in[1];   // (512, 64, 1024)
    const float* W   = (const float*)d_in[2];   // (1024, 2048)
    const float* vec = (const float*)d_in[4];   // (1024, 1)
    float* out = (float*)d_out;                 // (64, 1, 512)

    dim3 g1(H_DIM / 32, 4);
    compute_u_kernel<<<g1, 1024>>>(W, vec);
    dot_kernel<<<K2_GRID, 512>>>(hs);
    softmax_kernel<<<B_DIM, 512>>>(out);
}